// round 12
// baseline (speedup 1.0000x reference)
#include <cuda_runtime.h>

#define F 96
#define C4 24               // float4 chunks per feature row
#define CAPN 50240          // node capacity (N = 50000)
#define FULLM 0xffffffffu
#define ET 64               // edges per scatter tile
#define WPAD 100            // padded k-stride for transposed W in smem
#define XPAD 100            // padded k-stride for x tile in smem
#define GR 64               // gemm rows per block
#define SMEMSZ ((F * WPAD + GR * XPAD) * 4)   // 64000 bytes

// ---- scratch (__device__ globals; accessed ONLY by name in device code) ----
__device__ int    g_degi[CAPN];        // zeroed statically; re-zeroed in gemm1
__device__ float  g_dinv[CAPN];
__device__ float4 g_xs  [CAPN * C4];   // x pre-scaled by dinv[row]
__device__ float4 g_agg1[CAPN * C4];   // scatter target 1
__device__ float4 g_h1s [CAPN * C4];   // dinv[row] * relu((A x)@W1 + b1)
__device__ float4 g_agg2[CAPN * C4];   // scatter target 2

template <int SEL> __device__ __forceinline__ float4* buf();
template <> __device__ __forceinline__ float4* buf<0>() { return g_xs;   }
template <> __device__ __forceinline__ float4* buf<1>() { return g_agg1; }
template <> __device__ __forceinline__ float4* buf<2>() { return g_h1s;  }
template <> __device__ __forceinline__ float4* buf<3>() { return g_agg2; }

__device__ __forceinline__ void red4(float4* p, float4 v) { atomicAdd(p, v); }

// packed f32x2 fma: a += v * m  (lanes independent)
__device__ __forceinline__ void fma2(unsigned long long& a,
                                     unsigned long long v,
                                     unsigned long long m) {
    asm volatile("fma.rn.f32x2 %0, %1, %2, %0;" : "+l"(a) : "l"(v), "l"(m));
}
__device__ __forceinline__ float sum2(unsigned long long a) {
    float2 f = *reinterpret_cast<float2*>(&a);
    return f.x + f.y;
}

// ---------------------------------------------------------------------------
// launch 0: degree by dst; warp-aggregated for contiguous hub edges
// ---------------------------------------------------------------------------
__global__ void deg_kernel(const int* __restrict__ dst, int E) {
    int e = blockIdx.x * blockDim.x + threadIdx.x;
    bool valid = e < E;
    int d = valid ? dst[e] : -1;
    int d0 = __shfl_sync(FULLM, d, 0);
    unsigned bal = __ballot_sync(FULLM, valid && d == d0);
    if (bal == FULLM) {
        if ((threadIdx.x & 31) == 0) atomicAdd(&g_degi[d0], 32);
    } else if (valid) {
        atomicAdd(&g_degi[d], 1);
    }
}

// ---------------------------------------------------------------------------
// launch 1: fused init + xscale: dinv from degi, zero aggs, xs = x * dinv
// ---------------------------------------------------------------------------
__global__ void initx_kernel(const float4* __restrict__ x, int N) {
    int i = blockIdx.x * blockDim.x + threadIdx.x;   // float4 index
    int n4 = N * C4;
    if (i >= n4) return;
    int row = i / C4;
    int dg = g_degi[row];
    float dv = dg > 0 ? rsqrtf(fmaxf((float)dg, 1.f)) : 0.f;
    float4 z = make_float4(0.f, 0.f, 0.f, 0.f);
    g_agg1[i] = z;
    g_agg2[i] = z;
    float4 v = x[i];
    v.x *= dv; v.y *= dv; v.z *= dv; v.w *= dv;
    g_xs[i] = v;
    if ((i % C4) == 0) g_dinv[row] = dv;
}

// ---------------------------------------------------------------------------
// Scatter: agg[dst] += feat[src]   (feat already pre-scaled by dinv[src])
// 192 threads = 8 edge-slots x 24 chunks; 64-edge tiles staged in smem.
// Uniform-dst tiles (hub) reduce in registers+smem -> 1 atomic per chunk.
// ---------------------------------------------------------------------------
template <int IN, int OUT>
__global__ void __launch_bounds__(192) scatter_kernel(
        const int* __restrict__ src, const int* __restrict__ dst, int E) {
    const float4* __restrict__ feat = buf<IN>();
    float4* __restrict__ agg = buf<OUT>();

    const int t = threadIdx.x;
    const int c = t % C4;               // chunk 0..23
    const int g = t / C4;               // edge slot 0..7
    __shared__ int    ss[ET], sd[ET];
    __shared__ int    s_uni;
    __shared__ float4 sred[192];

    const int base = blockIdx.x * ET;
    const int m = min(ET, E - base);

    if (t == 0) s_uni = (m == ET) ? 1 : 0;
    if (t < m) { ss[t] = src[base + t]; sd[t] = dst[base + t]; }
    __syncthreads();
    if (t < m && sd[t] != sd[0]) s_uni = 0;
    __syncthreads();

    if (s_uni) {
        float4 acc = make_float4(0.f, 0.f, 0.f, 0.f);
#pragma unroll
        for (int r = 0; r < 8; r++) {
            int j = r * 8 + g;
            float4 v = __ldg(feat + (size_t)ss[j] * C4 + c);
            acc.x += v.x; acc.y += v.y; acc.z += v.z; acc.w += v.w;
        }
        sred[t] = acc;
        __syncthreads();
        if (g == 0) {
#pragma unroll
            for (int k = 1; k < 8; k++) {
                float4 v = sred[k * C4 + c];
                acc.x += v.x; acc.y += v.y; acc.z += v.z; acc.w += v.w;
            }
            red4(agg + (size_t)sd[0] * C4 + c, acc);
        }
    } else {
#pragma unroll
        for (int r = 0; r < 8; r++) {
            int j = r * 8 + g;
            if (j < m) {
                float4 v = __ldg(feat + (size_t)ss[j] * C4 + c);
                red4(agg + (size_t)sd[j] * C4 + c, v);
            }
        }
    }
}

// ---------------------------------------------------------------------------
// Register-tiled GEMM: block = 64 rows x 96 cols, 256 threads.
// Thread tile = 4 rows x 6 cols; colgrp = tid & 15 (col0 = colgrp*6),
// rowgrp = tid >> 4 (r0 = rowgrp*4). Accumulators k-parity packed (f32x2).
// Wt[col][k] (pad WPAD) and xs[row][k] (pad XPAD) in dynamic smem.
// ---------------------------------------------------------------------------
__device__ __forceinline__ void load_wt(float* Wt, const float* __restrict__ W,
                                        int t) {
    for (int i = t; i < F * F; i += 256) {
        int k = i / F, c = i % F;
        Wt[c * WPAD + k] = W[i];
    }
}

template <int IN>
__device__ __forceinline__ void load_xtile(float* xs, int row0, int N, int t) {
    const float4* __restrict__ a = buf<IN>();
    for (int i = t; i < GR * C4; i += 256) {     // float4 index within tile
        int r = i / C4, c4 = i % C4;
        int row = row0 + r;
        float4 v = make_float4(0.f, 0.f, 0.f, 0.f);
        if (row < N) {
            float dv = g_dinv[row];
            v = a[(size_t)row * C4 + c4];
            v.x *= dv; v.y *= dv; v.z *= dv; v.w *= dv;
        }
        *(float4*)&xs[r * XPAD + c4 * 4] = v;
    }
}

// 4 rows x 6 cols product; acc[r*6+c] packed over k-parity
__device__ __forceinline__ void mmkern(const float* Wt, const float* xs,
                                       int r0, int col0,
                                       unsigned long long acc[24]) {
#pragma unroll
    for (int k0 = 0; k0 < F; k0 += 4) {
        ulonglong2 xv[4];
#pragma unroll
        for (int r = 0; r < 4; r++)
            xv[r] = *(const ulonglong2*)&xs[(r0 + r) * XPAD + k0];
#pragma unroll
        for (int c = 0; c < 6; c++) {
            ulonglong2 wv = *(const ulonglong2*)&Wt[(col0 + c) * WPAD + k0];
#pragma unroll
            for (int r = 0; r < 4; r++) {
                fma2(acc[r * 6 + c], xv[r].x, wv.x);
                fma2(acc[r * 6 + c], xv[r].y, wv.y);
            }
        }
    }
}

// ---------------------------------------------------------------------------
// launch 3: gemm1: g_h1s = dinv .* relu((g_agg1 .* dinv) @ W1 + b1)
// Also re-zeroes g_degi for the next graph replay.
// ---------------------------------------------------------------------------
__global__ void __launch_bounds__(256) gemm1_kernel(
        const float* __restrict__ W, const float* __restrict__ b, int N) {
    extern __shared__ float sm[];
    float* Wt = sm;                  // F * WPAD
    float* xs = sm + F * WPAD;       // GR * XPAD
    const int t = threadIdx.x;
    {   // replay-reset of degree counters, piggybacked
        int gi = blockIdx.x * 256 + t;
        if (gi < N) g_degi[gi] = 0;
    }
    const int row0 = blockIdx.x * GR;
    load_wt(Wt, W, t);
    load_xtile<1>(xs, row0, N, t);
    __syncthreads();

    const int col0 = (t & 15) * 6;
    const int r0 = (t >> 4) * 4;
    unsigned long long acc[24] = {};
    mmkern(Wt, xs, r0, col0, acc);

#pragma unroll
    for (int r = 0; r < 4; r++) {
        int row = row0 + r0 + r;
        if (row < N) {
            float dv = g_dinv[row];
            float* o = (float*)g_h1s + (size_t)row * F + col0;
#pragma unroll
            for (int q = 0; q < 3; q++) {
                float2 v;
                v.x = fmaxf(sum2(acc[r*6 + q*2 + 0]) + b[col0 + q*2 + 0], 0.f) * dv;
                v.y = fmaxf(sum2(acc[r*6 + q*2 + 1]) + b[col0 + q*2 + 1], 0.f) * dv;
                *(float2*)&o[q * 2] = v;
            }
        }
    }
}

// ---------------------------------------------------------------------------
// launch 5: fused dual GEMM: mu = xa@W2a+b2a ; logstd = xa@W2b+b2b
// xa = g_agg2 .* dinv loaded once; Wa then Wb through the same smem buffer.
// ---------------------------------------------------------------------------
__global__ void __launch_bounds__(256) gemm2_kernel(
        const float* __restrict__ Wa, const float* __restrict__ ba,
        const float* __restrict__ Wb, const float* __restrict__ bb,
        float* __restrict__ out, int N) {
    extern __shared__ float sm[];
    float* Wt = sm;
    float* xs = sm + F * WPAD;
    const int t = threadIdx.x;
    const int row0 = blockIdx.x * GR;
    load_wt(Wt, Wa, t);
    load_xtile<3>(xs, row0, N, t);
    __syncthreads();

    const int col0 = (t & 15) * 6;
    const int r0 = (t >> 4) * 4;

    unsigned long long acca[24] = {};
    mmkern(Wt, xs, r0, col0, acca);

    __syncthreads();                 // all reads of Wa done
    load_wt(Wt, Wb, t);
    __syncthreads();
    unsigned long long accb[24] = {};
    mmkern(Wt, xs, r0, col0, accb);

    const size_t NF = (size_t)N * F;
#pragma unroll
    for (int r = 0; r < 4; r++) {
        int row = row0 + r0 + r;
        if (row < N) {
            size_t o = (size_t)row * F + col0;
#pragma unroll
            for (int q = 0; q < 3; q++) {
                float2 va, vb;
                va.x = sum2(acca[r*6 + q*2 + 0]) + ba[col0 + q*2 + 0];
                va.y = sum2(acca[r*6 + q*2 + 1]) + ba[col0 + q*2 + 1];
                vb.x = sum2(accb[r*6 + q*2 + 0]) + bb[col0 + q*2 + 0];
                vb.y = sum2(accb[r*6 + q*2 + 1]) + bb[col0 + q*2 + 1];
                *(float2*)&out[o + q * 2]      = va;
                *(float2*)&out[NF + o + q * 2] = vb;
            }
        }
    }
}

// ---------------------------------------------------------------------------
// inputs: x, W1, b1, W2a, b2a, W2b, b2b, edge_index[2,E]
// output: concat(mu [N,F], logstd [N,F])
//
// A_norm = D^-1/2 A D^-1/2 and GCN linearity give:
//   GCN(x) = (dinv .* (A @ (dinv .* x))) @ W + b
// -> pre-scale features, raw scatter-add over edges, post-scale at GEMM load.
// NOTE: no __device__ symbol is ever passed from host (ATS shadow-addr trap).
// ---------------------------------------------------------------------------
extern "C" void kernel_launch(void* const* d_in, const int* in_sizes, int n_in,
                              void* d_out, int out_size) {
    const float* x   = (const float*)d_in[0];
    const float* W1  = (const float*)d_in[1];
    const float* b1  = (const float*)d_in[2];
    const float* W2a = (const float*)d_in[3];
    const float* b2a = (const float*)d_in[4];
    const float* W2b = (const float*)d_in[5];
    const float* b2b = (const float*)d_in[6];
    const int*   ei  = (const int*)d_in[7];

    const int N = in_sizes[0] / F;
    const int E = in_sizes[7] / 2;
    const int* src = ei;
    const int* dst = ei + E;
    float* out = (float*)d_out;

    // allow 64KB dynamic smem for the gemm kernels (idempotent, capture-safe)
    static int s_attr_done = 0;
    if (!s_attr_done) {
        cudaFuncSetAttribute(gemm1_kernel,
            cudaFuncAttributeMaxDynamicSharedMemorySize, SMEMSZ);
        cudaFuncSetAttribute(gemm2_kernel,
            cudaFuncAttributeMaxDynamicSharedMemorySize, SMEMSZ);
        s_attr_done = 1;
    }

    const int TB = 256;
    int eg  = (E + TB - 1) / TB;
    int f4g = (N * C4 + TB - 1) / TB;
    int sg  = (E + ET - 1) / ET;
    int gg  = (N + GR - 1) / GR;

    deg_kernel  <<<eg, TB>>>(dst, E);                    // 0
    initx_kernel<<<f4g, TB>>>((const float4*)x, N);      // 1
    scatter_kernel<0, 1><<<sg, 192>>>(src, dst, E);      // 2: xs  -> agg1
    gemm1_kernel<<<gg, TB, SMEMSZ>>>(W1, b1, N);         // 3: -> h1s (+deg reset)
    scatter_kernel<2, 3><<<sg, 192>>>(src, dst, E);      // 4: h1s -> agg2
    gemm2_kernel<<<gg, TB, SMEMSZ>>>(W2a, b2a, W2b, b2b, out, N); // 5
}

// round 13
// speedup vs baseline: 1.0379x; 1.0379x over previous
#include <cuda_runtime.h>

#define F 96
#define C4 24               // float4 chunks per feature row
#define CAPN 50240          // node capacity (N = 50000)
#define FULLM 0xffffffffu
#define ET 64               // edges per scatter tile
#define WPAD 100            // padded k-stride for transposed W in smem
#define XPAD 100            // padded k-stride for x tile in smem
#define GR 64               // gemm rows per block
#define SMEMSZ ((F * WPAD + GR * XPAD) * 4)   // 64000 bytes

// ---- scratch (__device__ globals; accessed ONLY by name in device code) ----
__device__ int    g_degi[CAPN];        // zeroed statically; re-zeroed in gemm1
__device__ float  g_dinv[CAPN];
__device__ float4 g_xs  [CAPN * C4];   // x pre-scaled by dinv[row]
__device__ float4 g_agg1[CAPN * C4];   // scatter target 1
__device__ float4 g_h1s [CAPN * C4];   // dinv[row] * relu((A x)@W1 + b1)
__device__ float4 g_agg2[CAPN * C4];   // scatter target 2

template <int SEL> __device__ __forceinline__ float4* buf();
template <> __device__ __forceinline__ float4* buf<0>() { return g_xs;   }
template <> __device__ __forceinline__ float4* buf<1>() { return g_agg1; }
template <> __device__ __forceinline__ float4* buf<2>() { return g_h1s;  }
template <> __device__ __forceinline__ float4* buf<3>() { return g_agg2; }

__device__ __forceinline__ void red4(float4* p, float4 v) { atomicAdd(p, v); }

// packed f32x2 fma: a += v * m  (lanes independent)
__device__ __forceinline__ void fma2(unsigned long long& a,
                                     unsigned long long v,
                                     unsigned long long m) {
    asm volatile("fma.rn.f32x2 %0, %1, %2, %0;" : "+l"(a) : "l"(v), "l"(m));
}
__device__ __forceinline__ float sum2(unsigned long long a) {
    float2 f = *reinterpret_cast<float2*>(&a);
    return f.x + f.y;
}

// ---------------------------------------------------------------------------
// launch 0: degree by dst; warp-aggregated for contiguous hub edges
// ---------------------------------------------------------------------------
__global__ void deg_kernel(const int* __restrict__ dst, int E) {
    int e = blockIdx.x * blockDim.x + threadIdx.x;
    bool valid = e < E;
    int d = valid ? dst[e] : -1;
    int d0 = __shfl_sync(FULLM, d, 0);
    unsigned bal = __ballot_sync(FULLM, valid && d == d0);
    if (bal == FULLM) {
        if ((threadIdx.x & 31) == 0) atomicAdd(&g_degi[d0], 32);
    } else if (valid) {
        atomicAdd(&g_degi[d], 1);
    }
}

// ---------------------------------------------------------------------------
// launch 1: fused init + xscale: dinv from degi, zero aggs, xs = x * dinv
// ---------------------------------------------------------------------------
__global__ void initx_kernel(const float4* __restrict__ x, int N) {
    int i = blockIdx.x * blockDim.x + threadIdx.x;   // float4 index
    int n4 = N * C4;
    if (i >= n4) return;
    int row = i / C4;
    int dg = g_degi[row];
    float dv = dg > 0 ? rsqrtf(fmaxf((float)dg, 1.f)) : 0.f;
    float4 z = make_float4(0.f, 0.f, 0.f, 0.f);
    g_agg1[i] = z;
    g_agg2[i] = z;
    float4 v = x[i];
    v.x *= dv; v.y *= dv; v.z *= dv; v.w *= dv;
    g_xs[i] = v;
    if ((i % C4) == 0) g_dinv[row] = dv;
}

// ---------------------------------------------------------------------------
// Scatter: agg[dst] += feat[src]   (feat already pre-scaled by dinv[src])
// 192 threads = 8 edge-slots x 24 chunks; 64-edge tiles staged in smem.
// Uniform-dst tiles (hub) reduce in registers+smem -> 1 atomic per chunk.
// ---------------------------------------------------------------------------
template <int IN, int OUT>
__global__ void __launch_bounds__(192) scatter_kernel(
        const int* __restrict__ src, const int* __restrict__ dst, int E) {
    const float4* __restrict__ feat = buf<IN>();
    float4* __restrict__ agg = buf<OUT>();

    const int t = threadIdx.x;
    const int c = t % C4;               // chunk 0..23
    const int g = t / C4;               // edge slot 0..7
    __shared__ int    ss[ET], sd[ET];
    __shared__ int    s_uni;
    __shared__ float4 sred[192];

    const int base = blockIdx.x * ET;
    const int m = min(ET, E - base);

    if (t == 0) s_uni = (m == ET) ? 1 : 0;
    if (t < m) { ss[t] = src[base + t]; sd[t] = dst[base + t]; }
    __syncthreads();
    if (t < m && sd[t] != sd[0]) s_uni = 0;
    __syncthreads();

    if (s_uni) {
        float4 acc = make_float4(0.f, 0.f, 0.f, 0.f);
#pragma unroll
        for (int r = 0; r < 8; r++) {
            int j = r * 8 + g;
            float4 v = __ldg(feat + (size_t)ss[j] * C4 + c);
            acc.x += v.x; acc.y += v.y; acc.z += v.z; acc.w += v.w;
        }
        sred[t] = acc;
        __syncthreads();
        if (g == 0) {
#pragma unroll
            for (int k = 1; k < 8; k++) {
                float4 v = sred[k * C4 + c];
                acc.x += v.x; acc.y += v.y; acc.z += v.z; acc.w += v.w;
            }
            red4(agg + (size_t)sd[0] * C4 + c, acc);
        }
    } else {
#pragma unroll
        for (int r = 0; r < 8; r++) {
            int j = r * 8 + g;
            if (j < m) {
                float4 v = __ldg(feat + (size_t)ss[j] * C4 + c);
                red4(agg + (size_t)sd[j] * C4 + c, v);
            }
        }
    }
}

// ---------------------------------------------------------------------------
// Register-tiled GEMM: block = 64 rows x 96 cols, 256 threads.
// Thread tile = 4 rows x 6 cols. Accumulators k-parity packed (f32x2).
// Wt[col][k] (pad WPAD) and xs[row][k] (pad XPAD) in dynamic smem.
// ---------------------------------------------------------------------------
__device__ __forceinline__ void load_wt(float* Wt, const float* __restrict__ W,
                                        int t) {
    for (int i = t; i < F * F; i += 256) {
        int k = i / F, c = i % F;
        Wt[c * WPAD + k] = W[i];
    }
}

template <int IN>
__device__ __forceinline__ void load_xtile(float* xs, int row0, int N, int t) {
    const float4* __restrict__ a = buf<IN>();
    for (int i = t; i < GR * C4; i += 256) {     // float4 index within tile
        int r = i / C4, c4 = i % C4;
        int row = row0 + r;
        float4 v = make_float4(0.f, 0.f, 0.f, 0.f);
        if (row < N) {
            float dv = g_dinv[row];
            v = a[(size_t)row * C4 + c4];
            v.x *= dv; v.y *= dv; v.z *= dv; v.w *= dv;
        }
        *(float4*)&xs[r * XPAD + c4 * 4] = v;
    }
}

// 4 rows x 6 cols product; acc[r*6+c] packed over k-parity
__device__ __forceinline__ void mmkern(const float* Wt, const float* xs,
                                       int r0, int col0,
                                       unsigned long long acc[24]) {
#pragma unroll
    for (int k0 = 0; k0 < F; k0 += 4) {
        ulonglong2 xv[4];
#pragma unroll
        for (int r = 0; r < 4; r++)
            xv[r] = *(const ulonglong2*)&xs[(r0 + r) * XPAD + k0];
#pragma unroll
        for (int c = 0; c < 6; c++) {
            ulonglong2 wv = *(const ulonglong2*)&Wt[(col0 + c) * WPAD + k0];
#pragma unroll
            for (int r = 0; r < 4; r++) {
                fma2(acc[r * 6 + c], xv[r].x, wv.x);
                fma2(acc[r * 6 + c], xv[r].y, wv.y);
            }
        }
    }
}

// ---------------------------------------------------------------------------
// launch 3: gemm1: g_h1s = dinv .* relu((g_agg1 .* dinv) @ W1 + b1)
// Also re-zeroes g_degi for the next graph replay.
// ---------------------------------------------------------------------------
__global__ void __launch_bounds__(256) gemm1_kernel(
        const float* __restrict__ W, const float* __restrict__ b, int N) {
    extern __shared__ float sm[];
    float* Wt = sm;                  // F * WPAD
    float* xs = sm + F * WPAD;       // GR * XPAD
    const int t = threadIdx.x;
    {   // replay-reset of degree counters, piggybacked
        int gi = blockIdx.x * 256 + t;
        if (gi < N) g_degi[gi] = 0;
    }
    const int row0 = blockIdx.x * GR;
    load_wt(Wt, W, t);
    load_xtile<1>(xs, row0, N, t);
    __syncthreads();

    const int col0 = (t & 15) * 6;
    const int r0 = (t >> 4) * 4;
    unsigned long long acc[24] = {};
    mmkern(Wt, xs, r0, col0, acc);

#pragma unroll
    for (int r = 0; r < 4; r++) {
        int row = row0 + r0 + r;
        if (row < N) {
            float dv = g_dinv[row];
            float* o = (float*)g_h1s + (size_t)row * F + col0;
#pragma unroll
            for (int q = 0; q < 3; q++) {
                float2 v;
                v.x = fmaxf(sum2(acc[r*6 + q*2 + 0]) + b[col0 + q*2 + 0], 0.f) * dv;
                v.y = fmaxf(sum2(acc[r*6 + q*2 + 1]) + b[col0 + q*2 + 1], 0.f) * dv;
                *(float2*)&o[q * 2] = v;
            }
        }
    }
}

// ---------------------------------------------------------------------------
// launch 5: dual GEMM via gridDim.y: y=0 -> mu (W2a), y=1 -> logstd (W2b).
// Both phases run concurrently (independent CTAs) for better SM residency.
// ---------------------------------------------------------------------------
__global__ void __launch_bounds__(256) gemm2_kernel(
        const float* __restrict__ Wa, const float* __restrict__ ba,
        const float* __restrict__ Wb, const float* __restrict__ bb,
        float* __restrict__ out, int N) {
    extern __shared__ float sm[];
    float* Wt = sm;
    float* xs = sm + F * WPAD;
    const int t = threadIdx.x;
    const int row0 = blockIdx.x * GR;
    const int phase = blockIdx.y;
    const float* __restrict__ W = phase ? Wb : Wa;
    const float* __restrict__ b = phase ? bb : ba;
    float* __restrict__ o = out + (phase ? (size_t)N * F : 0);

    load_wt(Wt, W, t);
    load_xtile<3>(xs, row0, N, t);
    __syncthreads();

    const int col0 = (t & 15) * 6;
    const int r0 = (t >> 4) * 4;
    unsigned long long acc[24] = {};
    mmkern(Wt, xs, r0, col0, acc);

#pragma unroll
    for (int r = 0; r < 4; r++) {
        int row = row0 + r0 + r;
        if (row < N) {
            size_t off = (size_t)row * F + col0;
#pragma unroll
            for (int q = 0; q < 3; q++) {
                float2 v;
                v.x = sum2(acc[r*6 + q*2 + 0]) + b[col0 + q*2 + 0];
                v.y = sum2(acc[r*6 + q*2 + 1]) + b[col0 + q*2 + 1];
                *(float2*)&o[off + q * 2] = v;
            }
        }
    }
}

// ---------------------------------------------------------------------------
// inputs: x, W1, b1, W2a, b2a, W2b, b2b, edge_index[2,E]
// output: concat(mu [N,F], logstd [N,F])
//
// A_norm = D^-1/2 A D^-1/2 and GCN linearity give:
//   GCN(x) = (dinv .* (A @ (dinv .* x))) @ W + b
// -> pre-scale features, raw scatter-add over edges, post-scale at GEMM load.
// NOTE: no __device__ symbol is ever passed from host (ATS shadow-addr trap).
// ---------------------------------------------------------------------------
extern "C" void kernel_launch(void* const* d_in, const int* in_sizes, int n_in,
                              void* d_out, int out_size) {
    const float* x   = (const float*)d_in[0];
    const float* W1  = (const float*)d_in[1];
    const float* b1  = (const float*)d_in[2];
    const float* W2a = (const float*)d_in[3];
    const float* b2a = (const float*)d_in[4];
    const float* W2b = (const float*)d_in[5];
    const float* b2b = (const float*)d_in[6];
    const int*   ei  = (const int*)d_in[7];

    const int N = in_sizes[0] / F;
    const int E = in_sizes[7] / 2;
    const int* src = ei;
    const int* dst = ei + E;
    float* out = (float*)d_out;

    // full shared carveout + 64KB dynamic smem for the gemm kernels
    // (idempotent host-side attribute sets; execute at capture time)
    cudaFuncSetAttribute(gemm1_kernel,
        cudaFuncAttributeMaxDynamicSharedMemorySize, SMEMSZ);
    cudaFuncSetAttribute(gemm2_kernel,
        cudaFuncAttributeMaxDynamicSharedMemorySize, SMEMSZ);
    cudaFuncSetAttribute(gemm1_kernel,
        cudaFuncAttributePreferredSharedMemoryCarveout, 100);
    cudaFuncSetAttribute(gemm2_kernel,
        cudaFuncAttributePreferredSharedMemoryCarveout, 100);

    const int TB = 256;
    int eg  = (E + TB - 1) / TB;
    int f4g = (N * C4 + TB - 1) / TB;
    int sg  = (E + ET - 1) / ET;
    int gg  = (N + GR - 1) / GR;

    deg_kernel  <<<eg, TB>>>(dst, E);                    // 0
    initx_kernel<<<f4g, TB>>>((const float4*)x, N);      // 1
    scatter_kernel<0, 1><<<sg, 192>>>(src, dst, E);      // 2: xs  -> agg1
    gemm1_kernel<<<gg, TB, SMEMSZ>>>(W1, b1, N);         // 3: -> h1s (+deg reset)
    scatter_kernel<2, 3><<<sg, 192>>>(src, dst, E);      // 4: h1s -> agg2
    gemm2_kernel<<<dim3(gg, 2), TB, SMEMSZ>>>(W2a, b2a, W2b, b2b, out, N); // 5
}